// round 3
// baseline (speedup 1.0000x reference)
#include <cuda_runtime.h>

#define NN 8192
#define DD 128
#define CC 100
#define HB 64    // hist/scatter blocks, 128 rows each
#define SB 128   // stats blocks, 64 rows each

// ---------------- scratch (no allocations allowed) ----------------
__device__ double g_partialS[SB];
__device__ float  g_partialM[SB][DD];
__device__ double g_termAll;
__device__ int    g_counts[HB][CC];
__device__ int    g_classOff[CC + 1];
__device__ int    g_blockOff[HB][CC];
__device__ int    g_perm[NN];
__device__ double g_contrib[CC];
__device__ int    g_ymode;   // 1 = int64 labels, 0 = int32 labels

// ---------------- y dtype detection (data-determined, deterministic) ------
// int64 labels in [0,100) stored little-endian look like [v,0,v,0,...] as i32.
__global__ void k_detect(const int* y32) {
    __shared__ int anyOdd;
    if (threadIdx.x == 0) anyOdd = 0;
    __syncthreads();
    int local = 0;
    for (int i = threadIdx.x; i < NN; i += blockDim.x) {
        if ((i & 1) && y32[i] != 0) local = 1;   // odd i32 word nonzero => int32 layout
    }
    if (local) atomicOr(&anyOdd, 1);
    __syncthreads();
    if (threadIdx.x == 0) g_ymode = anyOdd ? 0 : 1;
}

__device__ __forceinline__ int load_label(const void* y, int i) {
    if (g_ymode) return (int)((const long long*)y)[i];
    return ((const int*)y)[i];
}

// ---------------- class histogram (deterministic int atomics) -------------
__global__ void k_hist(const void* y) {
    __shared__ int h[CC];
    int t = threadIdx.x;                    // 128 threads
    if (t < CC) h[t] = 0;
    __syncthreads();
    int c = load_label(y, blockIdx.x * 128 + t);
    atomicAdd(&h[c], 1);
    __syncthreads();
    if (t < CC) g_counts[blockIdx.x][t] = h[t];
}

// ---------------- offsets: per-class scan over blocks + class scan -------
__global__ void k_offsets() {
    __shared__ int tot[CC];
    int t = threadIdx.x;                    // 128 threads
    if (t < CC) {
        int run = 0;
        for (int b = 0; b < HB; b++) { g_blockOff[b][t] = run; run += g_counts[b][t]; }
        tot[t] = run;
    }
    __syncthreads();
    if (t == 0) {
        int run = 0;
        for (int c = 0; c < CC; c++) { g_classOff[c] = run; run += tot[c]; }
        g_classOff[CC] = run;
    }
}

// ---------------- stable scatter (sequential replay per block) ------------
__global__ void k_scatter(const void* y) {
    __shared__ int lc[CC];
    int t = threadIdx.x;
    if (t < CC) lc[t] = 0;
    __syncthreads();
    if (t == 0) {
        int base = blockIdx.x * 128;
        for (int r = 0; r < 128; r++) {
            int c = load_label(y, base + r);
            int pos = g_classOff[c] + g_blockOff[blockIdx.x][c] + lc[c]++;
            g_perm[pos] = base + r;
        }
    }
}

// ---------------- stats: S = sum(x^2), m = column sums -------------------
__global__ void k_stats(const float* __restrict__ x) {
    __shared__ float sm[256], ss[256];
    int t = threadIdx.x;                    // 256 threads
    int c = t & 127, half = t >> 7;
    float mloc = 0.f, sloc = 0.f;
    int base = blockIdx.x * 64;
    #pragma unroll 8
    for (int i = 0; i < 32; i++) {
        float v = x[(base + 2 * i + half) * DD + c];
        mloc += v; sloc += v * v;
    }
    sm[t] = mloc; ss[t] = sloc;
    __syncthreads();
    if (t < 128) g_partialM[blockIdx.x][t] = sm[t] + sm[t + 128];
    for (int s = 128; s > 0; s >>= 1) {
        if (t < s) ss[t] += ss[t + s];
        __syncthreads();
    }
    if (t == 0) g_partialS[blockIdx.x] = (double)ss[0];
}

__global__ void k_finalstats() {
    __shared__ double red[128];
    int t = threadIdx.x;                    // 128 threads
    double mc = 0.0;
    for (int b = 0; b < SB; b++) mc += (double)g_partialM[b][t];
    red[t] = mc * mc;
    __syncthreads();
    for (int s = 64; s > 0; s >>= 1) {
        if (t < s) red[t] += red[t + s];
        __syncthreads();
    }
    if (t == 0) {
        double S = 0.0;
        for (int b = 0; b < SB; b++) S += g_partialS[b];
        g_termAll = 2.0 * (double)NN * S - 2.0 * red[0];
    }
}

// ---------------- per-class pairwise (the real work) ---------------------
// Tile TI=96 rows, k-chunk 32, 16x16 threads, 6x6 micro-tile per thread.
#define TI 96
#define KC 32

__global__ void __launch_bounds__(256, 1) k_pairs(const float* __restrict__ x) {
    const int cls = blockIdx.x;
    const int off = g_classOff[cls];
    const int n   = g_classOff[cls + 1] - off;

    __shared__ float At[KC][TI];
    __shared__ float Bt[KC][TI];
    __shared__ float sqA[TI], sqB[TI];
    __shared__ double red[256];

    const int t = threadIdx.x;
    const int tx = t & 15, ty = t >> 4;
    const int i0 = ty * 6, j0 = tx * 6;

    float Asum = 0.f, Bsum = 0.f;

    for (int it = 0; it < n; it += TI) {
        for (int jt = 0; jt < n; jt += TI) {
            float acc[6][6];
            #pragma unroll
            for (int a = 0; a < 6; a++)
                #pragma unroll
                for (int b = 0; b < 6; b++) acc[a][b] = 0.f;

            float sa = 0.f, sb = 0.f;   // per-row sq partials (threads <96 / <192)

            for (int kc = 0; kc < DD; kc += KC) {
                __syncthreads();   // protect previous-iter readers of At/Bt
                // load 96 rows x 32 cols for both tiles, k-major in smem
                for (int idx = t; idx < TI * (KC / 4); idx += 256) {
                    int r = idx % TI;
                    int q = idx / TI;                      // 0..7
                    int gi = it + r;
                    int ga = g_perm[off + (gi < n ? gi : 0)];
                    float4 v = *(const float4*)(x + ga * DD + kc + q * 4);
                    At[q * 4 + 0][r] = v.x; At[q * 4 + 1][r] = v.y;
                    At[q * 4 + 2][r] = v.z; At[q * 4 + 3][r] = v.w;
                    int gj = jt + r;
                    int gb = g_perm[off + (gj < n ? gj : 0)];
                    float4 w = *(const float4*)(x + gb * DD + kc + q * 4);
                    Bt[q * 4 + 0][r] = w.x; Bt[q * 4 + 1][r] = w.y;
                    Bt[q * 4 + 2][r] = w.z; Bt[q * 4 + 3][r] = w.w;
                }
                __syncthreads();

                // row-norm partials
                if (t < TI) {
                    float s = 0.f;
                    #pragma unroll 8
                    for (int kk = 0; kk < KC; kk++) { float v = At[kk][t]; s += v * v; }
                    sa += s;
                } else if (t < 2 * TI) {
                    float s = 0.f;
                    int r = t - TI;
                    #pragma unroll 8
                    for (int kk = 0; kk < KC; kk++) { float v = Bt[kk][r]; s += v * v; }
                    sb += s;
                }

                // dot micro-kernel
                #pragma unroll 4
                for (int kk = 0; kk < KC; kk++) {
                    const float2* ap = (const float2*)&At[kk][i0];
                    const float2* bp = (const float2*)&Bt[kk][j0];
                    float2 a01 = ap[0], a23 = ap[1], a45 = ap[2];
                    float2 b01 = bp[0], b23 = bp[1], b45 = bp[2];
                    float a[6] = {a01.x, a01.y, a23.x, a23.y, a45.x, a45.y};
                    float b[6] = {b01.x, b01.y, b23.x, b23.y, b45.x, b45.y};
                    #pragma unroll
                    for (int ii = 0; ii < 6; ii++)
                        #pragma unroll
                        for (int jj = 0; jj < 6; jj++)
                            acc[ii][jj] = fmaf(a[ii], b[jj], acc[ii][jj]);
                }
            }

            if (t < TI) sqA[t] = sa;
            else if (t < 2 * TI) sqB[t - TI] = sb;
            __syncthreads();

            #pragma unroll
            for (int ii = 0; ii < 6; ii++) {
                #pragma unroll
                for (int jj = 0; jj < 6; jj++) {
                    int gi = it + i0 + ii, gj = jt + j0 + jj;
                    if (gi < n && gj < n) {
                        float d = sqA[i0 + ii] + sqB[j0 + jj] - 2.f * acc[ii][jj];
                        d = fmaxf(d, 0.f);                 // clamp like reference
                        Asum += d;                         // similar-pair d (to subtract)
                        Bsum += fmaxf(1.0f - d, 0.f);      // hinge, margin = 1.0
                    }
                }
            }
        }
    }

    red[t] = (double)Bsum - (double)Asum;
    __syncthreads();
    for (int s = 128; s > 0; s >>= 1) {
        if (t < s) red[t] += red[t + s];
        __syncthreads();
    }
    if (t == 0) g_contrib[cls] = red[0];
}

// ---------------- final combine ------------------------------------------
__global__ void k_final(float* out) {
    if (threadIdx.x == 0) {
        double tot = g_termAll;
        for (int c = 0; c < CC; c++) tot += g_contrib[c];
        out[0] = (float)(tot / ((double)NN * (double)NN));
    }
}

extern "C" void kernel_launch(void* const* d_in, const int* in_sizes, int n_in,
                              void* d_out, int out_size) {
    const float* x = (const float*)d_in[0];
    const void*  y = d_in[1];

    k_detect<<<1, 256>>>((const int*)y);
    k_hist<<<HB, 128>>>(y);
    k_offsets<<<1, 128>>>();
    k_scatter<<<HB, 128>>>(y);
    k_stats<<<SB, 256>>>(x);
    k_finalstats<<<1, 128>>>();
    k_pairs<<<CC, 256>>>(x);
    k_final<<<1, 32>>>((float*)d_out);
}

// round 5
// speedup vs baseline: 1.3883x; 1.3883x over previous
#include <cuda_runtime.h>

#define NN 8192
#define DD 128
#define CC 100
#define HB 64      // hist/scatter blocks, 128 rows each
#define GRID 152   // main kernel blocks (one per SM on GB300)
#define TI 96
#define KC 32
#define MAXT 7400  // >= worst-case sum of ceil(n_c/TI)^2 (single class: 86^2=7396)

// ---------------- scratch (device globals; no allocation allowed) --------
__device__ int    g_counts[HB][CC];
__device__ int    g_classOff[CC + 1];
__device__ int    g_blockOff[HB][CC];
__device__ int    g_perm[NN];
__device__ int    g_taskC[MAXT], g_taskI[MAXT], g_taskJ[MAXT];
__device__ int    g_ntasks;
__device__ double g_tileRes[MAXT];
__device__ double g_partialS[GRID];
__device__ float  g_partialM[GRID][DD];
__device__ int    g_ticket;       // zero-init; last block resets to 0 for graph replay

__device__ __forceinline__ float f2lo(unsigned long long v) { return __uint_as_float((unsigned)v); }
__device__ __forceinline__ float f2hi(unsigned long long v) { return __uint_as_float((unsigned)(v >> 32)); }

// int64 labels in [0,100) stored LE look like [v,0,v,0,...] as int32 words.
// Per-block local detection (data-determined, deterministic).
__device__ __forceinline__ int detect_mode_block(const int* y32, int t, int nthr) {
    __shared__ int s_mode;
    if (t == 0) s_mode = 1;
    __syncthreads();
    int bad = 0;
    for (int i = t; i < NN / 2; i += nthr)
        if (y32[2 * i + 1] != 0) bad = 1;        // nonzero odd word => int32 layout
    if (bad) atomicExch(&s_mode, 0);
    __syncthreads();
    return s_mode;                                // 1 = int64, 0 = int32
}

// ---------------- class histogram --------------------------------------
__global__ void k_hist(const int* __restrict__ y32) {
    __shared__ int h[CC];
    int t = threadIdx.x;                          // 128 threads
    if (t < CC) h[t] = 0;
    int mode = detect_mode_block(y32, t, 128);
    __syncthreads();
    int i = blockIdx.x * 128 + t;
    int c = mode ? y32[2 * i] : y32[i];
    atomicAdd(&h[c], 1);
    __syncthreads();
    if (t < CC) g_counts[blockIdx.x][t] = h[t];
}

// ---------------- offsets + flat tile-task list --------------------------
__global__ void k_offsets() {
    __shared__ int tot[CC];
    int t = threadIdx.x;                          // 128 threads
    if (t < CC) {
        int run = 0;
        for (int b = 0; b < HB; b++) { g_blockOff[b][t] = run; run += g_counts[b][t]; }
        tot[t] = run;
    }
    __syncthreads();
    if (t == 0) {
        int run = 0;
        for (int c = 0; c < CC; c++) { g_classOff[c] = run; run += tot[c]; }
        g_classOff[CC] = run;
        int nt = 0;
        for (int c = 0; c < CC; c++) {
            int n = tot[c];
            int m = (n + TI - 1) / TI;
            for (int a = 0; a < m; a++)
                for (int b = 0; b < m; b++) {
                    g_taskC[nt] = c; g_taskI[nt] = a * TI; g_taskJ[nt] = b * TI; nt++;
                }
        }
        g_ntasks = nt;
    }
}

// ---------------- stable scatter (parallel within-block rank) ------------
__global__ void k_scatter(const int* __restrict__ y32) {
    __shared__ int lab[128];
    int t = threadIdx.x;                          // 128 threads
    int mode = detect_mode_block(y32, t, 128);
    int base = blockIdx.x * 128;
    int c = mode ? y32[2 * (base + t)] : y32[base + t];
    lab[t] = c;
    __syncthreads();
    int rank = 0;
    for (int k = 0; k < t; k++) rank += (lab[k] == c);
    g_perm[g_classOff[c] + g_blockOff[blockIdx.x][c] + rank] = base + t;
}

// ---------------- main fused kernel: stats + tiles + final ---------------
__global__ void __launch_bounds__(256, 1) k_main(const float* __restrict__ x,
                                                 float* __restrict__ out) {
    __shared__ float At2[KC][2 * TI];   // A tile, each value DUPLICATED {v,v}
    __shared__ float Bt[KC][TI];
    __shared__ int   rowsA[TI], rowsB[TI];
    __shared__ float sqA[TI], sqB[TI];
    __shared__ double red[256];
    __shared__ float s_sm[256], s_ss[256];
    __shared__ int   s_isLast;

    const int t = threadIdx.x;
    const int bid = blockIdx.x;
    const int tx = t & 15, ty = t >> 4;
    const int i0 = ty * 6, j0 = tx * 6;

    // ---- stats slice: S = sum(x^2), m = column sums (rows bid, bid+GRID, ...)
    {
        int c = t & 127, h = t >> 7;
        float m = 0.f, s = 0.f;
        #pragma unroll 4
        for (int w = h; bid + GRID * w < NN; w += 2) {
            float v = x[(bid + GRID * w) * DD + c];
            m += v; s += v * v;
        }
        s_sm[t] = m; s_ss[t] = s;
        __syncthreads();
        if (t < 128) g_partialM[bid][t] = s_sm[t] + s_sm[t + 128];
        for (int s2 = 128; s2 > 0; s2 >>= 1) {
            if (t < s2) s_ss[t] += s_ss[t + s2];
            __syncthreads();
        }
        if (t == 0) g_partialS[bid] = (double)s_ss[0];
    }

    // ---- tile tasks
    const int ntasks = g_ntasks;
    for (int task = bid; task < ntasks; task += GRID) {
        const int cls = g_taskC[task], it = g_taskI[task], jt = g_taskJ[task];
        const int off = g_classOff[cls];
        const int n = g_classOff[cls + 1] - off;

        if (t < TI)            { int gi = it + t;      rowsA[t]      = g_perm[off + (gi < n ? gi : 0)]; }
        else if (t < 2 * TI)   { int r = t - TI, gj = jt + r; rowsB[r] = g_perm[off + (gj < n ? gj : 0)]; }

        unsigned long long acc[6][3];
        #pragma unroll
        for (int a = 0; a < 6; a++)
            #pragma unroll
            for (int b = 0; b < 3; b++) acc[a][b] = 0ull;
        float sa = 0.f, sb = 0.f;

        for (int kc = 0; kc < DD; kc += KC) {
            __syncthreads();   // rowsA/B ready; previous readers of tiles done
            for (int idx = t; idx < TI * (KC / 4); idx += 256) {
                int r = idx % TI, q = idx / TI;        // q in 0..7
                float4 v = *(const float4*)(x + rowsA[r] * DD + kc + q * 4);
                *(float2*)&At2[q * 4 + 0][2 * r] = make_float2(v.x, v.x);
                *(float2*)&At2[q * 4 + 1][2 * r] = make_float2(v.y, v.y);
                *(float2*)&At2[q * 4 + 2][2 * r] = make_float2(v.z, v.z);
                *(float2*)&At2[q * 4 + 3][2 * r] = make_float2(v.w, v.w);
                float4 w = *(const float4*)(x + rowsB[r] * DD + kc + q * 4);
                Bt[q * 4 + 0][r] = w.x; Bt[q * 4 + 1][r] = w.y;
                Bt[q * 4 + 2][r] = w.z; Bt[q * 4 + 3][r] = w.w;
            }
            __syncthreads();

            // row-norm partials (warps 0-5)
            if (t < TI) {
                float s = 0.f;
                #pragma unroll 8
                for (int kk = 0; kk < KC; kk++) { float v = At2[kk][2 * t]; s += v * v; }
                sa += s;
            } else if (t < 2 * TI) {
                float s = 0.f; int r = t - TI;
                #pragma unroll 8
                for (int kk = 0; kk < KC; kk++) { float v = Bt[kk][r]; s += v * v; }
                sb += s;
            }

            // f32x2 dot micro-kernel: 18 FFMA2 + 6 LDS per k
            #pragma unroll 8
            for (int kk = 0; kk < KC; kk++) {
                const unsigned long long* ap = (const unsigned long long*)&At2[kk][2 * i0];
                const unsigned long long* bp = (const unsigned long long*)&Bt[kk][j0];
                unsigned long long b0 = bp[0], b1 = bp[1], b2 = bp[2];
                #pragma unroll
                for (int ii = 0; ii < 6; ii++) {
                    unsigned long long av = ap[ii];
                    asm("fma.rn.f32x2 %0, %1, %2, %0;" : "+l"(acc[ii][0]) : "l"(av), "l"(b0));
                    asm("fma.rn.f32x2 %0, %1, %2, %0;" : "+l"(acc[ii][1]) : "l"(av), "l"(b1));
                    asm("fma.rn.f32x2 %0, %1, %2, %0;" : "+l"(acc[ii][2]) : "l"(av), "l"(b2));
                }
            }
        }

        if (t < TI) sqA[t] = sa;
        else if (t < 2 * TI) sqB[t - TI] = sb;
        __syncthreads();

        double lsum = 0.0;
        #pragma unroll
        for (int ii = 0; ii < 6; ii++) {
            int gi = it + i0 + ii;
            float sqa = sqA[i0 + ii];
            #pragma unroll
            for (int jc = 0; jc < 3; jc++) {
                int gj = jt + j0 + 2 * jc;
                float d0 = f2lo(acc[ii][jc]), d1 = f2hi(acc[ii][jc]);
                if (gi < n && gj < n) {
                    float d = fmaxf(sqa + sqB[j0 + 2 * jc] - 2.f * d0, 0.f);
                    lsum += (double)(fmaxf(1.0f - d, 0.f) - d);   // hinge(margin=1) - similar d
                }
                if (gi < n && gj + 1 < n) {
                    float d = fmaxf(sqa + sqB[j0 + 2 * jc + 1] - 2.f * d1, 0.f);
                    lsum += (double)(fmaxf(1.0f - d, 0.f) - d);
                }
            }
        }
        red[t] = lsum;
        __syncthreads();
        for (int s2 = 128; s2 > 0; s2 >>= 1) {
            if (t < s2) red[t] += red[t + s2];
            __syncthreads();
        }
        if (t == 0) g_tileRes[task] = red[0];
    }

    // ---- last-block final combine (deterministic fixed-order reductions)
    if (t == 0) {
        __threadfence();
        int v = atomicAdd(&g_ticket, 1);
        s_isLast = (v == GRID - 1);
    }
    __syncthreads();
    if (s_isLast) {
        // ||m||^2
        double mc = 0.0;
        if (t < 128) {
            #pragma unroll 8
            for (int b = 0; b < GRID; b++) mc += (double)g_partialM[b][t];
        }
        red[t] = mc * mc;
        __syncthreads();
        for (int s2 = 128; s2 > 0; s2 >>= 1) {
            if (t < s2) red[t] += red[t + s2];
            __syncthreads();
        }
        double msq = red[0];
        __syncthreads();
        // 2N*S + sum of tile contributions
        double v = 0.0;
        for (int i = t; i < GRID; i += 256) v += 2.0 * (double)NN * g_partialS[i];
        for (int i = t; i < ntasks; i += 256) v += g_tileRes[i];
        red[t] = v;
        __syncthreads();
        for (int s2 = 128; s2 > 0; s2 >>= 1) {
            if (t < s2) red[t] += red[t + s2];
            __syncthreads();
        }
        if (t == 0) {
            double total = red[0] - 2.0 * msq;
            out[0] = (float)(total / ((double)NN * (double)NN));
            g_ticket = 0;   // reset for next graph replay
        }
    }
}

extern "C" void kernel_launch(void* const* d_in, const int* in_sizes, int n_in,
                              void* d_out, int out_size) {
    const float* x = (const float*)d_in[0];
    const int* y32 = (const int*)d_in[1];

    k_hist<<<HB, 128>>>(y32);
    k_offsets<<<1, 128>>>();
    k_scatter<<<HB, 128>>>(y32);
    k_main<<<GRID, 256>>>(x, (float*)d_out);
}

// round 7
// speedup vs baseline: 1.4685x; 1.0578x over previous
#include <cuda_runtime.h>

#define NN 8192
#define DD 128
#define CC 100
#define HBLK 64          // label chunks of 128 rows
#define GRID 148         // <= SM count at occupancy 1 -> all CTAs co-resident
#define TI 96
#define MAXT 7400        // worst case: one class of 8192 -> ceil(8192/96)^2 = 7396
#define SMEM_DYN (2 * DD * TI * 4)   // At + Bt, 96 KB

typedef unsigned long long ull;

// ---------------- device scratch (zero-initialized; counters self-reset) --
__device__ int    g_counts[HBLK][CC];
__device__ int    g_classOff[CC + 1];
__device__ int    g_blockOff[HBLK][CC];
__device__ int    g_perm[NN];
__device__ int    g_taskC[MAXT], g_taskI[MAXT], g_taskJ[MAXT];
__device__ int    g_ntasks;
__device__ double g_tileRes[MAXT];
__device__ double g_partialS[GRID];
__device__ float  g_partialM[GRID][DD];
__device__ unsigned g_barCnt;   // grid barrier (cumulative); reset by last block
__device__ int    g_ticket;     // final-combine ticket; reset by last block

__device__ __forceinline__ float f2lo(ull v) { return __uint_as_float((unsigned)v); }
__device__ __forceinline__ float f2hi(ull v) { return __uint_as_float((unsigned)(v >> 32)); }

// cumulative-threshold grid barrier; all GRID blocks are co-resident.
__device__ __forceinline__ void grid_barrier(unsigned target) {
    __syncthreads();
    if (threadIdx.x == 0) {
        __threadfence();
        atomicAdd(&g_barCnt, 1u);
        while (atomicAdd(&g_barCnt, 0u) < target) { }
        __threadfence();
    }
    __syncthreads();
}

// int64 labels in [0,100) stored LE look like [v,0,v,0,...] as int32 words.
__device__ __forceinline__ int detect_mode(const int* y32, int t, int nthr) {
    __shared__ int s_mode;
    if (t == 0) s_mode = 1;
    __syncthreads();
    int bad = 0;
    for (int i = t; i < NN / 2; i += nthr)
        if (y32[2 * i + 1] != 0) bad = 1;
    if (bad) atomicExch(&s_mode, 0);
    __syncthreads();
    return s_mode;                 // 1 = int64, 0 = int32
}

__global__ void __launch_bounds__(256, 1) k_main(const float* __restrict__ x,
                                                 const int* __restrict__ y32,
                                                 float* __restrict__ out) {
    extern __shared__ float dyn[];
    float* At = dyn;               // [DD][TI] k-major
    float* Bt = dyn + DD * TI;     // [DD][TI] k-major
    __shared__ float  sqA[TI], sqB[TI];
    __shared__ double red[256];
    __shared__ float  s_sm[256], s_ss[256];
    __shared__ int    s_h[CC];
    __shared__ int    s_lab[128];
    __shared__ int    s_tot[CC];
    __shared__ int    s_isLast;

    const int t = threadIdx.x;
    const int bid = blockIdx.x;
    const int tx = t & 15, ty = t >> 4;
    const int i0 = ty * 6, j0 = tx * 6;

    // =========== Phase A: stats slice + (blocks 0..63) label histogram ====
    {
        int c = t & 127, h = t >> 7;
        float m = 0.f, s = 0.f;
        #pragma unroll 4
        for (int w = h; bid + GRID * w < NN; w += 2) {
            float v = x[(bid + GRID * w) * DD + c];
            m += v; s += v * v;
        }
        s_sm[t] = m; s_ss[t] = s;
        __syncthreads();
        if (t < 128) g_partialM[bid][t] = s_sm[t] + s_sm[t + 128];
        for (int s2 = 128; s2 > 0; s2 >>= 1) {
            if (t < s2) s_ss[t] += s_ss[t + s2];
            __syncthreads();
        }
        if (t == 0) g_partialS[bid] = (double)s_ss[0];
    }
    int mode = 1;
    if (bid < HBLK) {
        mode = detect_mode(y32, t, 256);
        if (t < CC) s_h[t] = 0;
        __syncthreads();
        if (t < 128) {
            int i = bid * 128 + t;
            int c = mode ? y32[2 * i] : y32[i];
            atomicAdd(&s_h[c], 1);
        }
        __syncthreads();
        if (t < CC) g_counts[bid][t] = s_h[t];
    }
    grid_barrier(GRID);

    // =========== Phase B: block 0 builds offsets + flat tile-task list ====
    if (bid == 0) {
        if (t < CC) {
            int run = 0;
            for (int b = 0; b < HBLK; b++) { g_blockOff[b][t] = run; run += g_counts[b][t]; }
            s_tot[t] = run;
        }
        __syncthreads();
        if (t == 0) {
            int run = 0;
            for (int c = 0; c < CC; c++) { g_classOff[c] = run; run += s_tot[c]; }
            g_classOff[CC] = run;
            int nt = 0;
            for (int c = 0; c < CC; c++) {
                int m2 = (s_tot[c] + TI - 1) / TI;
                for (int a = 0; a < m2 && nt < MAXT; a++)
                    for (int b = 0; b < m2 && nt < MAXT; b++) {
                        g_taskC[nt] = c; g_taskI[nt] = a * TI; g_taskJ[nt] = b * TI; nt++;
                    }
            }
            g_ntasks = nt;
        }
    }
    grid_barrier(2 * GRID);

    // =========== Phase C: blocks 0..63 stable scatter (parallel rank) =====
    if (bid < HBLK && t < 128) {
        int base = bid * 128;
        int c = mode ? y32[2 * (base + t)] : y32[base + t];
        s_lab[t] = c;
        __syncwarp();
    }
    if (bid < HBLK) {
        __syncthreads();
        if (t < 128) {
            int c = s_lab[t];
            int rank = 0;
            for (int k = 0; k < t; k++) rank += (s_lab[k] == c);
            g_perm[g_classOff[c] + g_blockOff[bid][c] + rank] = bid * 128 + t;
        }
    }
    grid_barrier(3 * GRID);

    // =========== Phase D: tile tasks =====================================
    const int ntasks = g_ntasks;
    for (int task = bid; task < ntasks; task += GRID) {
        const int cls = g_taskC[task], it = g_taskI[task], jt = g_taskJ[task];
        const int off = g_classOff[cls];
        const int n = g_classOff[cls + 1] - off;

        __syncthreads();   // previous task's readers done before overwriting tiles

        // ---- load full 96x128 tiles, row per thread, norms for free ----
        if (t < 2 * TI) {
            int isB = t >= TI;
            int r = isB ? t - TI : t;
            int gidx = (isB ? jt : it) + r;
            int row = g_perm[off + (gidx < n ? gidx : 0)];
            const float4* src = (const float4*)(x + row * DD);
            float* dst = (isB ? Bt : At) + r;
            float s = 0.f;
            #pragma unroll
            for (int q = 0; q < DD / 4; q++) {
                float4 v = src[q];
                s += v.x * v.x + v.y * v.y + v.z * v.z + v.w * v.w;
                dst[(4 * q + 0) * TI] = v.x;
                dst[(4 * q + 1) * TI] = v.y;
                dst[(4 * q + 2) * TI] = v.z;
                dst[(4 * q + 3) * TI] = v.w;
            }
            if (isB) sqB[r] = s; else sqA[r] = s;
        }
        __syncthreads();

        // ---- 128-deep f32x2 micro-kernel: i-paired accumulators ----
        // acc[p][j] = { dot(i0+2p, j0+j), dot(i0+2p+1, j0+j) }
        ull acc[3][6];
        #pragma unroll
        for (int p = 0; p < 3; p++)
            #pragma unroll
            for (int j = 0; j < 6; j++) acc[p][j] = 0ull;

        #pragma unroll 4
        for (int k = 0; k < DD; k++) {
            const float* ar = At + k * TI + i0;
            const float* br = Bt + k * TI + j0;
            ull a0 = *(const ull*)(ar);       // {a_i0,   a_i0+1}
            ull a1 = *(const ull*)(ar + 2);
            ull a2 = *(const ull*)(ar + 4);
            float2 b01 = *(const float2*)(br);
            float2 b23 = *(const float2*)(br + 2);
            float2 b45 = *(const float2*)(br + 4);
            ull bb[6];
            asm("mov.b64 %0, {%1,%1};" : "=l"(bb[0]) : "r"(__float_as_uint(b01.x)));
            asm("mov.b64 %0, {%1,%1};" : "=l"(bb[1]) : "r"(__float_as_uint(b01.y)));
            asm("mov.b64 %0, {%1,%1};" : "=l"(bb[2]) : "r"(__float_as_uint(b23.x)));
            asm("mov.b64 %0, {%1,%1};" : "=l"(bb[3]) : "r"(__float_as_uint(b23.y)));
            asm("mov.b64 %0, {%1,%1};" : "=l"(bb[4]) : "r"(__float_as_uint(b45.x)));
            asm("mov.b64 %0, {%1,%1};" : "=l"(bb[5]) : "r"(__float_as_uint(b45.y)));
            #pragma unroll
            for (int j = 0; j < 6; j++) {
                asm("fma.rn.f32x2 %0, %1, %2, %0;" : "+l"(acc[0][j]) : "l"(a0), "l"(bb[j]));
                asm("fma.rn.f32x2 %0, %1, %2, %0;" : "+l"(acc[1][j]) : "l"(a1), "l"(bb[j]));
                asm("fma.rn.f32x2 %0, %1, %2, %0;" : "+l"(acc[2][j]) : "l"(a2), "l"(bb[j]));
            }
        }

        // ---- epilogue: d -> (hinge - d) over valid same-class pairs ----
        double lsum = 0.0;
        #pragma unroll
        for (int p = 0; p < 3; p++) {
            int giL = it + i0 + 2 * p, giH = giL + 1;
            float sqaL = sqA[i0 + 2 * p], sqaH = sqA[i0 + 2 * p + 1];
            #pragma unroll
            for (int j = 0; j < 6; j++) {
                int gj = jt + j0 + j;
                if (gj < n) {
                    float sqb = sqB[j0 + j];
                    float dL = f2lo(acc[p][j]), dH = f2hi(acc[p][j]);
                    if (giL < n) {
                        float d = fmaxf(sqaL + sqb - 2.f * dL, 0.f);
                        lsum += (double)(fmaxf(1.0f - d, 0.f) - d);
                    }
                    if (giH < n) {
                        float d = fmaxf(sqaH + sqb - 2.f * dH, 0.f);
                        lsum += (double)(fmaxf(1.0f - d, 0.f) - d);
                    }
                }
            }
        }
        red[t] = lsum;
        __syncthreads();
        for (int s2 = 128; s2 > 0; s2 >>= 1) {
            if (t < s2) red[t] += red[t + s2];
            __syncthreads();
        }
        if (t == 0) g_tileRes[task] = red[0];
    }

    // =========== final combine: last block, deterministic fixed order =====
    if (t == 0) {
        __threadfence();
        int v = atomicAdd(&g_ticket, 1);
        s_isLast = (v == GRID - 1);
    }
    __syncthreads();
    if (s_isLast) {
        double mc = 0.0;
        if (t < 128) {
            #pragma unroll 8
            for (int b = 0; b < GRID; b++) mc += (double)g_partialM[b][t];
        }
        red[t] = mc * mc;
        __syncthreads();
        for (int s2 = 128; s2 > 0; s2 >>= 1) {
            if (t < s2) red[t] += red[t + s2];
            __syncthreads();
        }
        double msq = red[0];
        __syncthreads();
        double v = 0.0;
        for (int i = t; i < GRID; i += 256) v += 2.0 * (double)NN * g_partialS[i];
        for (int i = t; i < ntasks; i += 256) v += g_tileRes[i];
        red[t] = v;
        __syncthreads();
        for (int s2 = 128; s2 > 0; s2 >>= 1) {
            if (t < s2) red[t] += red[t + s2];
            __syncthreads();
        }
        if (t == 0) {
            double total = red[0] - 2.0 * msq;
            out[0] = (float)(total / ((double)NN * (double)NN));
            g_ticket = 0;      // reset for next graph replay
            g_barCnt = 0u;
        }
    }
}

extern "C" void kernel_launch(void* const* d_in, const int* in_sizes, int n_in,
                              void* d_out, int out_size) {
    const float* x = (const float*)d_in[0];
    const int* y32 = (const int*)d_in[1];

    static int attr_set = 0;
    if (!attr_set) {
        cudaFuncSetAttribute(k_main, cudaFuncAttributeMaxDynamicSharedMemorySize, SMEM_DYN);
        attr_set = 1;
    }
    k_main<<<GRID, 256, SMEM_DYN>>>(x, y32, (float*)d_out);
}